// round 11
// baseline (speedup 1.0000x reference)
#include <cuda_runtime.h>
#include <cuda_fp16.h>
#include <cstdint>

#define H 1024
#define BATCH 8
#define SEQ 2048
#define ROWS (BATCH * SEQ)   // 16384

// ---- GEMM tile config: CTA 128x256x64, 8 warps (2x4), warp tile 64x64 ----
#define BM 128
#define BN 256
#define BK 64
#define STG_BYTES (BM * 128 + BN * 128)      // A 16KB + B 32KB = 48KB per stage
#define SMEM_BYTES (2 * STG_BYTES)           // 96KB -> 2 CTAs/SM (16 warps/SM)

// ---------------- scratch (static device globals; no allocation) ----------------
__device__ float  g_xqn_f32[(size_t)ROWS * H];          // 64 MB
__device__ __half g_xqn_h [(size_t)ROWS * H];           // 32 MB
__device__ __half g_kr    [(size_t)ROWS * H];           // 32 MB
__device__ __half g_vr    [(size_t)ROWS * H];           // 32 MB
__device__ __half g_qr    [(size_t)ROWS * H];           // 32 MB (pre-scaled 1/32)
__device__ __half g_E     [(size_t)BATCH * SEQ * SEQ];  // 64 MB
__device__ __half g_qWh   [(size_t)H * H];              // 2 MB
__device__ float  g_gate  [H];
__device__ float  g_Zpart [BATCH * 256];
__device__ float  g_Zinv  [BATCH];

__device__ __forceinline__ float sigmoidf(float x) { return 1.f / (1.f + expf(-x)); }

__device__ __forceinline__ void store_h4(__half* p, float a, float b, float c, float d) {
    __half2 lo = __floats2half2_rn(a, b);
    __half2 hi = __floats2half2_rn(c, d);
    uint2 u;
    u.x = *reinterpret_cast<unsigned*>(&lo);
    u.y = *reinterpret_cast<unsigned*>(&hi);
    *reinterpret_cast<uint2*>(p) = u;
}

__device__ __forceinline__ uint32_t smem_u32(const void* p) {
    uint32_t a;
    asm("{ .reg .u64 t; cvta.to.shared.u64 t, %1; cvt.u32.u64 %0, t; }" : "=r"(a) : "l"(p));
    return a;
}

__device__ __forceinline__ void cp16(uint32_t dst, const void* src) {
    asm volatile("cp.async.cg.shared.global [%0], [%1], 16;" :: "r"(dst), "l"(src) : "memory");
}
#define CP_COMMIT() asm volatile("cp.async.commit_group;" ::: "memory")
#define CP_WAIT1()  asm volatile("cp.async.wait_group 1;" ::: "memory")
#define CP_WAIT0()  asm volatile("cp.async.wait_group 0;" ::: "memory")

__device__ __forceinline__ void ldsm4(uint32_t* r, uint32_t a) {
    asm volatile("ldmatrix.sync.aligned.m8n8.x4.shared.b16 {%0,%1,%2,%3}, [%4];"
                 : "=r"(r[0]), "=r"(r[1]), "=r"(r[2]), "=r"(r[3]) : "r"(a));
}
__device__ __forceinline__ void ldsm4t(uint32_t* r, uint32_t a) {
    asm volatile("ldmatrix.sync.aligned.m8n8.x4.trans.shared.b16 {%0,%1,%2,%3}, [%4];"
                 : "=r"(r[0]), "=r"(r[1]), "=r"(r[2]), "=r"(r[3]) : "r"(a));
}

// f16 x f16 -> f16 accumulate (2-reg accumulator = 4 halves)
__device__ __forceinline__ void mma_h(uint32_t* d, const uint32_t* a, uint32_t b0, uint32_t b1) {
    asm volatile(
        "mma.sync.aligned.m16n8k16.row.col.f16.f16.f16.f16 "
        "{%0,%1}, {%2,%3,%4,%5}, {%6,%7}, {%0,%1};"
        : "+r"(d[0]), "+r"(d[1])
        : "r"(a[0]), "r"(a[1]), "r"(a[2]), "r"(a[3]), "r"(b0), "r"(b1));
}

// ---------------- small prep kernels ----------------
__global__ void cvt_qw_kernel(const float* __restrict__ qW) {
    int i = blockIdx.x * blockDim.x + threadIdx.x;
    if (i < H * H) g_qWh[i] = __float2half(qW[i]);
}

__global__ void gate_kernel(const float* __restrict__ v_prime,
                            const float* __restrict__ v1W, const float* __restrict__ v1b,
                            const float* __restrict__ v2W, const float* __restrict__ v2b) {
    int warp = (blockIdx.x * blockDim.x + threadIdx.x) >> 5;
    int lane = threadIdx.x & 31;
    if (warp >= H) return;
    float s1 = 0.f, s2 = 0.f;
    for (int i = lane; i < H; i += 32) {
        float vp = sigmoidf(v_prime[i]);
        s1 += vp * v1W[warp * H + i];
        s2 += vp * v2W[warp * H + i];
    }
#pragma unroll
    for (int o = 16; o; o >>= 1) {
        s1 += __shfl_xor_sync(0xffffffffu, s1, o);
        s2 += __shfl_xor_sync(0xffffffffu, s2, o);
    }
    if (lane == 0)
        g_gate[warp] = sigmoidf(s1 + v1b[warp]) * tanhf(s2 + v2b[warp]);
}

// ---------------- fused dual LayerNorm + elementwise ----------------
__global__ void ln_kernel(const float* __restrict__ x,
                          const float* __restrict__ qn_w, const float* __restrict__ qn_b,
                          const float* __restrict__ kvn_w, const float* __restrict__ kvn_b,
                          const float* __restrict__ k_prime) {
    int row = blockIdx.x;
    int tid = threadIdx.x;
    size_t base = (size_t)row * H;
    float4 v = *reinterpret_cast<const float4*>(x + base + tid * 4);
    float s  = v.x + v.y + v.z + v.w;
    float ss = v.x * v.x + v.y * v.y + v.z * v.z + v.w * v.w;
#pragma unroll
    for (int o = 16; o; o >>= 1) {
        s  += __shfl_xor_sync(0xffffffffu, s, o);
        ss += __shfl_xor_sync(0xffffffffu, ss, o);
    }
    __shared__ float shs[8], shss[8];
    int w = tid >> 5, l = tid & 31;
    if (l == 0) { shs[w] = s; shss[w] = ss; }
    __syncthreads();
    float ts = 0.f, tss = 0.f;
#pragma unroll
    for (int i = 0; i < 8; i++) { ts += shs[i]; tss += shss[i]; }
    float mean = ts * (1.f / H);
    float var  = tss * (1.f / H) - mean * mean;
    float rstd = rsqrtf(var + 1e-5f);

    int j = tid * 4;
    float4 qw  = *reinterpret_cast<const float4*>(qn_w + j);
    float4 qb4 = *reinterpret_cast<const float4*>(qn_b + j);
    float4 kw  = *reinterpret_cast<const float4*>(kvn_w + j);
    float4 kb4 = *reinterpret_cast<const float4*>(kvn_b + j);
    float4 kp  = *reinterpret_cast<const float4*>(k_prime + j);
    float4 gt  = *reinterpret_cast<const float4*>(g_gate + j);

    float xh0 = (v.x - mean) * rstd, xh1 = (v.y - mean) * rstd;
    float xh2 = (v.z - mean) * rstd, xh3 = (v.w - mean) * rstd;

    float xq0 = xh0 * qw.x + qb4.x, xq1 = xh1 * qw.y + qb4.y;
    float xq2 = xh2 * qw.z + qb4.z, xq3 = xh3 * qw.w + qb4.w;
    float xk0 = xh0 * kw.x + kb4.x, xk1 = xh1 * kw.y + kb4.y;
    float xk2 = xh2 * kw.z + kb4.z, xk3 = xh3 * kw.w + kb4.w;

    *reinterpret_cast<float4*>(g_xqn_f32 + base + j) = make_float4(xq0, xq1, xq2, xq3);
    store_h4(g_xqn_h + base + j, xq0, xq1, xq2, xq3);
    store_h4(g_kr + base + j, xk0 * sigmoidf(kp.x), xk1 * sigmoidf(kp.y),
                              xk2 * sigmoidf(kp.z), xk3 * sigmoidf(kp.w));
    store_h4(g_vr + base + j, xk0 * gt.x, xk1 * gt.y, xk2 * gt.z, xk3 * gt.w);
}

// ---------------- pipelined f16 mma GEMM: 256 thr, 8 warps (2x4), warp 64x64 ----------------
// EK = 0: qr  = (xqn_h @ qWh^T + qb) * sigmoid(q') / 32   [B:(N,K)]   -> g_qr
// EK = 1: E   = exp(qr @ kr^T)                              [B:(N,K)]   -> g_E + Z partials
// EK = 2: out = (E @ vr) * Zinv[b] + xqn_f32                [B:(K,N)]   -> d_out
template<int EK>
__global__ void __launch_bounds__(256, 2)
gemm_mma(const float* __restrict__ e0, const float* __restrict__ e1,
         float* __restrict__ outf) {
    constexpr bool TRB = (EK == 2);
    constexpr int Kdim = (EK == 2) ? 2048 : 1024;
    constexpr int LDA  = (EK == 2) ? 2048 : 1024;   // elems
    constexpr int LDB  = 1024;                      // elems
    constexpr int KT   = Kdim / BK;

    extern __shared__ char smem[];
    uint32_t sm = smem_u32(smem);

    int tid  = threadIdx.x;
    int lane = tid & 31, w = tid >> 5;
    int wm = w >> 2, wn = w & 3;              // 2x4 warp grid, warp tile 64x64
    int bz = blockIdx.z;
    int m0 = blockIdx.y * BM, n0 = blockIdx.x * BN;

    const __half *A, *B;
    if (EK == 0)      { A = g_xqn_h;                        B = g_qWh; }
    else if (EK == 1) { A = g_qr + (size_t)bz * SEQ * H;    B = g_kr + (size_t)bz * SEQ * H; }
    else              { A = g_E  + (size_t)bz * SEQ * SEQ;  B = g_vr + (size_t)bz * SEQ * H; }

    // ---- A loader: 128 rows x 128B, 256 thr -> 4 iters of 32 rows ----
    int ar_ = tid >> 3, ac_ = tid & 7;
    uint32_t aswz = (uint32_t)((ac_ ^ (ar_ & 7)) << 4);
    const char* Ag = (const char*)(A + (size_t)(m0 + ar_) * LDA) + ac_ * 16;

    // ---- B loader ----
    // TRB: 64 k-rows x 512B (n256), 8 iters of 8 rows; pitch 512B
    // else: 256 n-rows x 128B, 8 iters of 32 rows
    int br_, bc_;
    uint32_t bswz;
    const char* Bg;
    if (TRB) {
        br_ = tid >> 5; bc_ = tid & 31;
        bswz = (uint32_t)((((bc_ & 7) ^ (br_ & 7)) | (bc_ & 24)) << 4);
        Bg = (const char*)(B + (size_t)br_ * LDB + n0) + bc_ * 16;
    } else {
        br_ = ar_; bc_ = ac_;
        bswz = aswz;
        Bg = (const char*)(B + (size_t)(n0 + br_) * LDB) + bc_ * 16;
    }

    auto load_tile = [&](int s, int kt) {
        uint32_t base = sm + s * STG_BYTES;
        const char* ag = Ag + (size_t)kt * (BK * 2);
#pragma unroll
        for (int i = 0; i < 4; i++)
            cp16(base + (uint32_t)(ar_ + i * 32) * 128 + aswz, ag + (size_t)i * 32 * LDA * 2);
        uint32_t bb = base + 16384u;
        if (TRB) {
            const char* bg = Bg + (size_t)kt * BK * LDB * 2;
#pragma unroll
            for (int i = 0; i < 8; i++)                      // rows step 8: (br&7) invariant
                cp16(bb + (uint32_t)(br_ + i * 8) * 512 + bswz, bg + (size_t)i * 8 * LDB * 2);
        } else {
            const char* bg = Bg + (size_t)kt * (BK * 2);
#pragma unroll
            for (int i = 0; i < 8; i++)
                cp16(bb + (uint32_t)(br_ + i * 32) * 128 + bswz, bg + (size_t)i * 32 * LDB * 2);
        }
    };

    load_tile(0, 0); CP_COMMIT();

    // f16 accumulators: warp 64x64 -> 4 mi x 8 n8, 2 regs each = 64 regs
    uint32_t acc[4][8][2];
#pragma unroll
    for (int i = 0; i < 4; i++)
#pragma unroll
        for (int j = 0; j < 8; j++) { acc[i][j][0] = 0u; acc[i][j][1] = 0u; }

    int l15 = lane & 15;
    int hi  = lane >> 4;

    // strength-reduced LDSM offsets; per-ks chunk walk: XOR 0x20,0x60,0x20, wrap 0x60
    uint32_t aoff[4], boff[4];
#pragma unroll
    for (int mi = 0; mi < 4; mi++) {
        int r = wm * 64 + mi * 16 + l15;
        aoff[mi] = (uint32_t)r * 128 + (uint32_t)((hi ^ (r & 7)) << 4);
    }
    if (TRB) {
#pragma unroll
        for (int nj = 0; nj < 4; nj++) {
            int cn = wn * 8 + nj * 2 + hi;   // n8-chunk within 32-chunk row
            boff[nj] = 16384u + (uint32_t)l15 * 512
                     + (uint32_t)((((cn & 7) ^ (l15 & 7)) | (cn & 24)) << 4);
        }
    } else {
#pragma unroll
        for (int nj = 0; nj < 4; nj++) {
            int r = wn * 64 + nj * 16 + l15;
            boff[nj] = 16384u + (uint32_t)r * 128 + (uint32_t)((hi ^ (r & 7)) << 4);
        }
    }

    for (int kt = 0; kt < KT; kt++) {
        __syncthreads();                      // prev compute done -> other stage reusable
        int s = kt & 1;
        uint32_t sbase = sm + s * STG_BYTES;

        if (kt + 1 < KT) {
            load_tile(s ^ 1, kt + 1);
            CP_COMMIT();
            CP_WAIT1();
        } else {
            CP_WAIT0();
        }
        __syncthreads();                      // stage s visible

#pragma unroll
        for (int ks = 0; ks < 4; ks++) {
            uint32_t arf[4][4], brf[4][4];
#pragma unroll
            for (int mi = 0; mi < 4; mi++)
                ldsm4(arf[mi], sbase + aoff[mi]);
            if (TRB) {
#pragma unroll
                for (int nj = 0; nj < 4; nj++)
                    ldsm4t(brf[nj], sbase + boff[nj]);
#pragma unroll
                for (int mi = 0; mi < 4; mi++)
#pragma unroll
                    for (int nj = 0; nj < 4; nj++) {
                        mma_h(acc[mi][nj * 2 + 0], arf[mi], brf[nj][0], brf[nj][1]);
                        mma_h(acc[mi][nj * 2 + 1], arf[mi], brf[nj][2], brf[nj][3]);
                    }
            } else {
#pragma unroll
                for (int nj = 0; nj < 4; nj++)
                    ldsm4(brf[nj], sbase + boff[nj]);
#pragma unroll
                for (int mi = 0; mi < 4; mi++)
#pragma unroll
                    for (int nj = 0; nj < 4; nj++) {
                        mma_h(acc[mi][nj * 2 + 0], arf[mi], brf[nj][0], brf[nj][2]);
                        mma_h(acc[mi][nj * 2 + 1], arf[mi], brf[nj][1], brf[nj][3]);
                    }
            }
            // advance to next k16 chunk
            const uint32_t adel = (ks == 1) ? 0x60u : 0x20u;
            const uint32_t rdel = (ks == 3) ? 0x60u : adel;
#pragma unroll
            for (int mi = 0; mi < 4; mi++) aoff[mi] ^= rdel;
            if (TRB) {
#pragma unroll
                for (int nj = 0; nj < 4; nj++)
                    boff[nj] = (ks == 3) ? boff[nj] - 3u * 8192u : boff[nj] + 8192u;
            } else {
#pragma unroll
                for (int nj = 0; nj < 4; nj++) boff[nj] ^= rdel;
            }
        }
    }

    // ---------------- register epilogue ----------------
    float zs = 0.f;
    float zi = (EK == 2) ? g_Zinv[bz] : 0.f;

#pragma unroll
    for (int nj = 0; nj < 8; nj++) {
        int col = n0 + wn * 64 + nj * 8 + (lane & 3) * 2;
        float b0 = 0.f, b1 = 0.f, p0 = 0.f, p1 = 0.f;
        if (EK == 0) {
            float2 bb = *reinterpret_cast<const float2*>(e0 + col);
            float2 pp = *reinterpret_cast<const float2*>(e1 + col);
            b0 = bb.x; b1 = bb.y;
            p0 = sigmoidf(pp.x) * 0.03125f;
            p1 = sigmoidf(pp.y) * 0.03125f;
        }
#pragma unroll
        for (int mi = 0; mi < 4; mi++) {
            int r0 = m0 + wm * 64 + mi * 16 + (lane >> 2);
            int r1 = r0 + 8;
            float2 cl = __half22float2(*reinterpret_cast<__half2*>(&acc[mi][nj][0]));
            float2 ch = __half22float2(*reinterpret_cast<__half2*>(&acc[mi][nj][1]));
            if (EK == 0) {
                __half2 u0 = __floats2half2_rn((cl.x + b0) * p0, (cl.y + b1) * p1);
                __half2 u1 = __floats2half2_rn((ch.x + b0) * p0, (ch.y + b1) * p1);
                *reinterpret_cast<__half2*>(g_qr + (size_t)r0 * H + col) = u0;
                *reinterpret_cast<__half2*>(g_qr + (size_t)r1 * H + col) = u1;
            } else if (EK == 1) {
                __half2 u0 = __floats2half2_rn(__expf(cl.x), __expf(cl.y));
                __half2 u1 = __floats2half2_rn(__expf(ch.x), __expf(ch.y));
                float2 d0 = __half22float2(u0), d1 = __half22float2(u1);
                zs += d0.x + d0.y + d1.x + d1.y;
                size_t bb = (size_t)bz * SEQ * SEQ;
                *reinterpret_cast<__half2*>(g_E + bb + (size_t)r0 * SEQ + col) = u0;
                *reinterpret_cast<__half2*>(g_E + bb + (size_t)r1 * SEQ + col) = u1;
            } else {
                size_t o0 = ((size_t)bz * SEQ + r0) * H + col;
                size_t o1 = ((size_t)bz * SEQ + r1) * H + col;
                float2 x0 = *reinterpret_cast<const float2*>(g_xqn_f32 + o0);
                float2 x1 = *reinterpret_cast<const float2*>(g_xqn_f32 + o1);
                *reinterpret_cast<float2*>(outf + o0) =
                    make_float2(cl.x * zi + x0.x, cl.y * zi + x0.y);
                *reinterpret_cast<float2*>(outf + o1) =
                    make_float2(ch.x * zi + x1.x, ch.y * zi + x1.y);
            }
        }
    }

    if (EK == 1) {
        __shared__ float red[8];
#pragma unroll
        for (int o = 16; o; o >>= 1) zs += __shfl_xor_sync(0xffffffffu, zs, o);
        if (lane == 0) red[w] = zs;
        __syncthreads();
        if (tid == 0) {
            float t = 0.f;
#pragma unroll
            for (int i = 0; i < 8; i++) t += red[i];
            g_Zpart[bz * 256 + blockIdx.y * gridDim.x + blockIdx.x] = t;
        }
    }
}

// deterministic fixed-order reduction -> 1/Z per batch
__global__ void zreduce_kernel() {
    int b = blockIdx.x, tid = threadIdx.x;
    __shared__ float sh[256];
    sh[tid] = g_Zpart[b * 256 + tid];
    __syncthreads();
    for (int o = 128; o; o >>= 1) {
        if (tid < o) sh[tid] += sh[tid + o];
        __syncthreads();
    }
    if (tid == 0) g_Zinv[b] = 1.f / sh[0];
}

// ---------------- launch ----------------
extern "C" void kernel_launch(void* const* d_in, const int* in_sizes, int n_in,
                              void* d_out, int out_size) {
    const float* x       = (const float*)d_in[0];
    const float* qn_w    = (const float*)d_in[1];
    const float* qn_b    = (const float*)d_in[2];
    const float* kvn_w   = (const float*)d_in[3];
    const float* kvn_b   = (const float*)d_in[4];
    const float* q_prime = (const float*)d_in[5];
    const float* k_prime = (const float*)d_in[6];
    const float* v_prime = (const float*)d_in[7];
    const float* qW      = (const float*)d_in[8];
    const float* qb      = (const float*)d_in[9];
    const float* v1W     = (const float*)d_in[10];
    const float* v1b     = (const float*)d_in[11];
    const float* v2W     = (const float*)d_in[12];
    const float* v2b     = (const float*)d_in[13];
    float* out = (float*)d_out;

    cudaFuncSetAttribute(gemm_mma<0>, cudaFuncAttributeMaxDynamicSharedMemorySize, SMEM_BYTES);
    cudaFuncSetAttribute(gemm_mma<1>, cudaFuncAttributeMaxDynamicSharedMemorySize, SMEM_BYTES);
    cudaFuncSetAttribute(gemm_mma<2>, cudaFuncAttributeMaxDynamicSharedMemorySize, SMEM_BYTES);

    cvt_qw_kernel<<<4096, 256>>>(qW);
    gate_kernel<<<128, 256>>>(v_prime, v1W, v1b, v2W, v2b);
    ln_kernel<<<ROWS, 256>>>(x, qn_w, qn_b, kvn_w, kvn_b, k_prime);

    // qr = (xqn @ qW^T + qb) * sigmoid(q') / 32
    gemm_mma<0><<<dim3(H / BN, ROWS / BM, 1), 256, SMEM_BYTES>>>(qb, q_prime, nullptr);
    // E = exp(qr @ kr^T) + tile partial sums
    gemm_mma<1><<<dim3(SEQ / BN, SEQ / BM, BATCH), 256, SMEM_BYTES>>>(nullptr, nullptr, nullptr);
    // Zinv[b] = 1 / sum(E_b)
    zreduce_kernel<<<BATCH, 256>>>();
    // out = (E @ vr) * Zinv + xqn
    gemm_mma<2><<<dim3(H / BN, SEQ / BM, BATCH), 256, SMEM_BYTES>>>(nullptr, nullptr, out);
}

// round 12
// speedup vs baseline: 1.0095x; 1.0095x over previous
#include <cuda_runtime.h>
#include <cuda_fp16.h>
#include <cstdint>

#define H 1024
#define BATCH 8
#define SEQ 2048
#define ROWS (BATCH * SEQ)   // 16384

// ---- GEMM tile config: CTA 128x128x64, 8 warps (2x4), warp tile 64x32 ----
#define BM 128
#define BN 128
#define BK 64
#define NSTG 3
#define STG_BYTES (2 * BM * BK * 2)          // A(16KB)+B(16KB) = 32KB per stage
#define SMEM_BYTES (NSTG * STG_BYTES)        // 96KB -> 2 CTAs/SM (16 warps/SM)

// ---------------- scratch (static device globals; no allocation) ----------------
__device__ __half g_xqn_h [(size_t)ROWS * H];           // 32 MB (GEMM A operand + residual)
__device__ __half g_kr    [(size_t)ROWS * H];           // 32 MB
__device__ __half g_vr    [(size_t)ROWS * H];           // 32 MB
__device__ __half g_qr    [(size_t)ROWS * H];           // 32 MB (pre-scaled 1/32)
__device__ __half g_E     [(size_t)BATCH * SEQ * SEQ];  // 64 MB
__device__ __half g_qWh   [(size_t)H * H];              // 2 MB
__device__ float  g_gate  [H];
__device__ float  g_Zpart [BATCH * 256];
__device__ float  g_Zinv  [BATCH];

__device__ __forceinline__ float sigmoidf(float x) { return 1.f / (1.f + expf(-x)); }

__device__ __forceinline__ void store_h4(__half* p, float a, float b, float c, float d) {
    __half2 lo = __floats2half2_rn(a, b);
    __half2 hi = __floats2half2_rn(c, d);
    uint2 u;
    u.x = *reinterpret_cast<unsigned*>(&lo);
    u.y = *reinterpret_cast<unsigned*>(&hi);
    *reinterpret_cast<uint2*>(p) = u;
}

__device__ __forceinline__ uint32_t smem_u32(const void* p) {
    uint32_t a;
    asm("{ .reg .u64 t; cvta.to.shared.u64 t, %1; cvt.u32.u64 %0, t; }" : "=r"(a) : "l"(p));
    return a;
}

__device__ __forceinline__ void cp16(uint32_t dst, const void* src) {
    asm volatile("cp.async.cg.shared.global [%0], [%1], 16;" :: "r"(dst), "l"(src) : "memory");
}
#define CP_COMMIT() asm volatile("cp.async.commit_group;" ::: "memory")
#define CP_WAIT1()  asm volatile("cp.async.wait_group 1;" ::: "memory")

__device__ __forceinline__ void ldsm4(uint32_t* r, uint32_t a) {
    asm volatile("ldmatrix.sync.aligned.m8n8.x4.shared.b16 {%0,%1,%2,%3}, [%4];"
                 : "=r"(r[0]), "=r"(r[1]), "=r"(r[2]), "=r"(r[3]) : "r"(a));
}
__device__ __forceinline__ void ldsm4t(uint32_t* r, uint32_t a) {
    asm volatile("ldmatrix.sync.aligned.m8n8.x4.trans.shared.b16 {%0,%1,%2,%3}, [%4];"
                 : "=r"(r[0]), "=r"(r[1]), "=r"(r[2]), "=r"(r[3]) : "r"(a));
}

// f16 x f16 -> f16 accumulate (2-reg accumulator = 4 halves)
__device__ __forceinline__ void mma_h(uint32_t* d, const uint32_t* a, uint32_t b0, uint32_t b1) {
    asm volatile(
        "mma.sync.aligned.m16n8k16.row.col.f16.f16.f16.f16 "
        "{%0,%1}, {%2,%3,%4,%5}, {%6,%7}, {%0,%1};"
        : "+r"(d[0]), "+r"(d[1])
        : "r"(a[0]), "r"(a[1]), "r"(a[2]), "r"(a[3]), "r"(b0), "r"(b1));
}

// ---------------- small prep kernels ----------------
__global__ void cvt_qw_kernel(const float* __restrict__ qW) {
    int i = blockIdx.x * blockDim.x + threadIdx.x;
    if (i < H * H) g_qWh[i] = __float2half(qW[i]);
}

__global__ void gate_kernel(const float* __restrict__ v_prime,
                            const float* __restrict__ v1W, const float* __restrict__ v1b,
                            const float* __restrict__ v2W, const float* __restrict__ v2b) {
    int warp = (blockIdx.x * blockDim.x + threadIdx.x) >> 5;
    int lane = threadIdx.x & 31;
    if (warp >= H) return;
    float s1 = 0.f, s2 = 0.f;
    for (int i = lane; i < H; i += 32) {
        float vp = sigmoidf(v_prime[i]);
        s1 += vp * v1W[warp * H + i];
        s2 += vp * v2W[warp * H + i];
    }
#pragma unroll
    for (int o = 16; o; o >>= 1) {
        s1 += __shfl_xor_sync(0xffffffffu, s1, o);
        s2 += __shfl_xor_sync(0xffffffffu, s2, o);
    }
    if (lane == 0)
        g_gate[warp] = sigmoidf(s1 + v1b[warp]) * tanhf(s2 + v2b[warp]);
}

// ---------------- fused dual LayerNorm + elementwise (f16 outputs only) ----------------
__global__ void ln_kernel(const float* __restrict__ x,
                          const float* __restrict__ qn_w, const float* __restrict__ qn_b,
                          const float* __restrict__ kvn_w, const float* __restrict__ kvn_b,
                          const float* __restrict__ k_prime) {
    int row = blockIdx.x;
    int tid = threadIdx.x;
    size_t base = (size_t)row * H;
    float4 v = *reinterpret_cast<const float4*>(x + base + tid * 4);
    float s  = v.x + v.y + v.z + v.w;
    float ss = v.x * v.x + v.y * v.y + v.z * v.z + v.w * v.w;
#pragma unroll
    for (int o = 16; o; o >>= 1) {
        s  += __shfl_xor_sync(0xffffffffu, s, o);
        ss += __shfl_xor_sync(0xffffffffu, ss, o);
    }
    __shared__ float shs[8], shss[8];
    int w = tid >> 5, l = tid & 31;
    if (l == 0) { shs[w] = s; shss[w] = ss; }
    __syncthreads();
    float ts = 0.f, tss = 0.f;
#pragma unroll
    for (int i = 0; i < 8; i++) { ts += shs[i]; tss += shss[i]; }
    float mean = ts * (1.f / H);
    float var  = tss * (1.f / H) - mean * mean;
    float rstd = rsqrtf(var + 1e-5f);

    int j = tid * 4;
    float4 qw  = *reinterpret_cast<const float4*>(qn_w + j);
    float4 qb4 = *reinterpret_cast<const float4*>(qn_b + j);
    float4 kw  = *reinterpret_cast<const float4*>(kvn_w + j);
    float4 kb4 = *reinterpret_cast<const float4*>(kvn_b + j);
    float4 kp  = *reinterpret_cast<const float4*>(k_prime + j);
    float4 gt  = *reinterpret_cast<const float4*>(g_gate + j);

    float xh0 = (v.x - mean) * rstd, xh1 = (v.y - mean) * rstd;
    float xh2 = (v.z - mean) * rstd, xh3 = (v.w - mean) * rstd;

    float xq0 = xh0 * qw.x + qb4.x, xq1 = xh1 * qw.y + qb4.y;
    float xq2 = xh2 * qw.z + qb4.z, xq3 = xh3 * qw.w + qb4.w;
    float xk0 = xh0 * kw.x + kb4.x, xk1 = xh1 * kw.y + kb4.y;
    float xk2 = xh2 * kw.z + kb4.z, xk3 = xh3 * kw.w + kb4.w;

    store_h4(g_xqn_h + base + j, xq0, xq1, xq2, xq3);
    store_h4(g_kr + base + j, xk0 * sigmoidf(kp.x), xk1 * sigmoidf(kp.y),
                              xk2 * sigmoidf(kp.z), xk3 * sigmoidf(kp.w));
    store_h4(g_vr + base + j, xk0 * gt.x, xk1 * gt.y, xk2 * gt.z, xk3 * gt.w);
}

// ---------------- pipelined f16 mma GEMM: 256 thr, 8 warps (2x4), warp 64x32 ----------------
// EK = 0: qr  = (xqn_h @ qWh^T + qb) * sigmoid(q') / 32   [B:(N,K)]   -> g_qr
// EK = 1: E   = exp(qr @ kr^T)                              [B:(N,K)]   -> g_E + Z partials
// EK = 2: out = (E @ vr) * Zinv[b] + xqn_h                  [B:(K,N)]   -> d_out (f32)
template<int EK>
__global__ void __launch_bounds__(256, 2)
gemm_mma(const float* __restrict__ e0, const float* __restrict__ e1,
         float* __restrict__ outf) {
    constexpr bool TRB = (EK == 2);
    constexpr int Kdim = (EK == 2) ? 2048 : 1024;
    constexpr int LDA  = (EK == 2) ? 2048 : 1024;   // elems
    constexpr int LDB  = 1024;                      // elems
    constexpr int KT   = Kdim / BK;

    extern __shared__ char smem[];
    uint32_t sm = smem_u32(smem);

    int tid  = threadIdx.x;
    int lane = tid & 31, w = tid >> 5;
    int wm = w >> 2, wn = w & 3;              // 2x4 warp grid, warp tile 64x32
    int bz = blockIdx.z;
    int m0 = blockIdx.y * BM, n0 = blockIdx.x * BN;

    const __half *A, *B;
    if (EK == 0)      { A = g_xqn_h;                        B = g_qWh; }
    else if (EK == 1) { A = g_qr + (size_t)bz * SEQ * H;    B = g_kr + (size_t)bz * SEQ * H; }
    else              { A = g_E  + (size_t)bz * SEQ * SEQ;  B = g_vr + (size_t)bz * SEQ * H; }

    // ---- A loader: 128 rows x 128B, 256 thr -> 4 iters of 32 rows ----
    int ar_ = tid >> 3, ac_ = tid & 7;
    uint32_t aswz = (uint32_t)((ac_ ^ (ar_ & 7)) << 4);
    const char* Ag = (const char*)(A + (size_t)(m0 + ar_) * LDA) + ac_ * 16;

    // ---- B loader ----
    int br_, bc_;
    uint32_t bswz;
    const char* Bg;
    if (TRB) {
        br_ = tid >> 4; bc_ = tid & 15;
        bswz = (uint32_t)((((bc_ & 7) ^ (br_ & 7)) | (bc_ & 8)) << 4);
        Bg = (const char*)(B + (size_t)br_ * LDB + n0) + bc_ * 16;
    } else {
        br_ = ar_; bc_ = ac_;
        bswz = aswz;
        Bg = (const char*)(B + (size_t)(n0 + br_) * LDB) + bc_ * 16;
    }

    auto load_tile = [&](int s, int kt) {
        uint32_t base = sm + s * STG_BYTES;
        const char* ag = Ag + (size_t)kt * (BK * 2);
#pragma unroll
        for (int i = 0; i < 4; i++)
            cp16(base + (uint32_t)(ar_ + i * 32) * 128 + aswz, ag + (size_t)i * 32 * LDA * 2);
        uint32_t bb = base + 16384u;
        if (TRB) {
            const char* bg = Bg + (size_t)kt * BK * LDB * 2;
#pragma unroll
            for (int i = 0; i < 4; i++)
                cp16(bb + (uint32_t)(br_ + i * 16) * 256 + bswz, bg + (size_t)i * 16 * LDB * 2);
        } else {
            const char* bg = Bg + (size_t)kt * (BK * 2);
#pragma unroll
            for (int i = 0; i < 4; i++)
                cp16(bb + (uint32_t)(br_ + i * 32) * 128 + bswz, bg + (size_t)i * 32 * LDB * 2);
        }
    };

    load_tile(0, 0); CP_COMMIT();
    load_tile(1, 1); CP_COMMIT();

    // f16 accumulators: warp 64x32 -> 4 mi x 4 n8, 2 regs each = 32 regs
    uint32_t acc[4][4][2];
#pragma unroll
    for (int i = 0; i < 4; i++)
#pragma unroll
        for (int j = 0; j < 4; j++) { acc[i][j][0] = 0u; acc[i][j][1] = 0u; }

    int l15 = lane & 15;
    int hi  = lane >> 4;
    int rlA = wm * 64 + l15;
    int rlB = wn * 32 + l15;
    int tK  = l15;                             // TRB: k-row within k16

    // strength-reduced LDSM offsets; per-ks chunk walk: XOR 0x20,0x60,0x20, wrap 0x60
    uint32_t aoff[4], boff[2];
#pragma unroll
    for (int mi = 0; mi < 4; mi++) {
        int r = rlA + mi * 16;
        aoff[mi] = (uint32_t)r * 128 + (uint32_t)((hi ^ (r & 7)) << 4);
    }
    if (TRB) {
#pragma unroll
        for (int nj = 0; nj < 2; nj++) {
            int cn = wn * 4 + nj * 2 + hi;
            boff[nj] = 16384u + (uint32_t)tK * 256
                     + (uint32_t)((((cn & 7) ^ (tK & 7)) | (cn & 8)) << 4);
        }
    } else {
#pragma unroll
        for (int nj = 0; nj < 2; nj++) {
            int r = rlB + nj * 16;
            boff[nj] = 16384u + (uint32_t)r * 128 + (uint32_t)((hi ^ (r & 7)) << 4);
        }
    }

    for (int kt = 0; kt < KT; kt++) {
        CP_WAIT1();
        __syncthreads();
        int s = kt % NSTG;
        uint32_t sbase = sm + s * STG_BYTES;

        int nt = kt + NSTG - 1;
        if (nt < KT) load_tile(nt % NSTG, nt);
        CP_COMMIT();

#pragma unroll
        for (int ks = 0; ks < 4; ks++) {
            uint32_t arf[4][4], brf[2][4];
#pragma unroll
            for (int mi = 0; mi < 4; mi++)
                ldsm4(arf[mi], sbase + aoff[mi]);
            if (TRB) {
#pragma unroll
                for (int nj = 0; nj < 2; nj++)
                    ldsm4t(brf[nj], sbase + boff[nj]);
#pragma unroll
                for (int mi = 0; mi < 4; mi++)
#pragma unroll
                    for (int nj = 0; nj < 2; nj++) {
                        mma_h(acc[mi][nj * 2 + 0], arf[mi], brf[nj][0], brf[nj][1]);
                        mma_h(acc[mi][nj * 2 + 1], arf[mi], brf[nj][2], brf[nj][3]);
                    }
            } else {
#pragma unroll
                for (int nj = 0; nj < 2; nj++)
                    ldsm4(brf[nj], sbase + boff[nj]);
#pragma unroll
                for (int mi = 0; mi < 4; mi++)
#pragma unroll
                    for (int nj = 0; nj < 2; nj++) {
                        mma_h(acc[mi][nj * 2 + 0], arf[mi], brf[nj][0], brf[nj][2]);
                        mma_h(acc[mi][nj * 2 + 1], arf[mi], brf[nj][1], brf[nj][3]);
                    }
            }
            // advance to next k16 chunk
            const uint32_t adel = (ks == 1) ? 0x60u : 0x20u;
            const uint32_t rdel = (ks == 3) ? 0x60u : adel;
#pragma unroll
            for (int mi = 0; mi < 4; mi++) aoff[mi] ^= rdel;
            if (TRB) {
#pragma unroll
                for (int nj = 0; nj < 2; nj++)
                    boff[nj] = (ks == 3) ? boff[nj] - 3u * 4096u : boff[nj] + 4096u;
            } else {
#pragma unroll
                for (int nj = 0; nj < 2; nj++) boff[nj] ^= rdel;
            }
        }
    }

    // ---------------- register epilogue ----------------
    float zs = 0.f;
    float zi = (EK == 2) ? g_Zinv[bz] : 0.f;

#pragma unroll
    for (int nj = 0; nj < 4; nj++) {
        int col = n0 + wn * 32 + nj * 8 + (lane & 3) * 2;
        float b0 = 0.f, b1 = 0.f, p0 = 0.f, p1 = 0.f;
        if (EK == 0) {
            float2 bb = *reinterpret_cast<const float2*>(e0 + col);
            float2 pp = *reinterpret_cast<const float2*>(e1 + col);
            b0 = bb.x; b1 = bb.y;
            p0 = sigmoidf(pp.x) * 0.03125f;
            p1 = sigmoidf(pp.y) * 0.03125f;
        }
#pragma unroll
        for (int mi = 0; mi < 4; mi++) {
            int r0 = m0 + wm * 64 + mi * 16 + (lane >> 2);
            int r1 = r0 + 8;
            float2 cl = __half22float2(*reinterpret_cast<__half2*>(&acc[mi][nj][0]));
            float2 ch = __half22float2(*reinterpret_cast<__half2*>(&acc[mi][nj][1]));
            if (EK == 0) {
                __half2 u0 = __floats2half2_rn((cl.x + b0) * p0, (cl.y + b1) * p1);
                __half2 u1 = __floats2half2_rn((ch.x + b0) * p0, (ch.y + b1) * p1);
                *reinterpret_cast<__half2*>(g_qr + (size_t)r0 * H + col) = u0;
                *reinterpret_cast<__half2*>(g_qr + (size_t)r1 * H + col) = u1;
            } else if (EK == 1) {
                __half2 u0 = __floats2half2_rn(__expf(cl.x), __expf(cl.y));
                __half2 u1 = __floats2half2_rn(__expf(ch.x), __expf(ch.y));
                float2 d0 = __half22float2(u0), d1 = __half22float2(u1);
                zs += d0.x + d0.y + d1.x + d1.y;
                size_t bb = (size_t)bz * SEQ * SEQ;
                *reinterpret_cast<__half2*>(g_E + bb + (size_t)r0 * SEQ + col) = u0;
                *reinterpret_cast<__half2*>(g_E + bb + (size_t)r1 * SEQ + col) = u1;
            } else {
                size_t o0 = ((size_t)bz * SEQ + r0) * H + col;
                size_t o1 = ((size_t)bz * SEQ + r1) * H + col;
                float2 x0 = __half22float2(*reinterpret_cast<const __half2*>(g_xqn_h + o0));
                float2 x1 = __half22float2(*reinterpret_cast<const __half2*>(g_xqn_h + o1));
                *reinterpret_cast<float2*>(outf + o0) =
                    make_float2(cl.x * zi + x0.x, cl.y * zi + x0.y);
                *reinterpret_cast<float2*>(outf + o1) =
                    make_float2(ch.x * zi + x1.x, ch.y * zi + x1.y);
            }
        }
    }

    if (EK == 1) {
        __shared__ float red[8];
#pragma unroll
        for (int o = 16; o; o >>= 1) zs += __shfl_xor_sync(0xffffffffu, zs, o);
        if (lane == 0) red[w] = zs;
        __syncthreads();
        if (tid == 0) {
            float t = 0.f;
#pragma unroll
            for (int i = 0; i < 8; i++) t += red[i];
            g_Zpart[bz * 256 + blockIdx.y * gridDim.x + blockIdx.x] = t;
        }
    }
}

// deterministic fixed-order reduction -> 1/Z per batch
__global__ void zreduce_kernel() {
    int b = blockIdx.x, tid = threadIdx.x;
    __shared__ float sh[256];
    sh[tid] = g_Zpart[b * 256 + tid];
    __syncthreads();
    for (int o = 128; o; o >>= 1) {
        if (tid < o) sh[tid] += sh[tid + o];
        __syncthreads();
    }
    if (tid == 0) g_Zinv[b] = 1.f / sh[0];
}

// ---------------- launch ----------------
extern "C" void kernel_launch(void* const* d_in, const int* in_sizes, int n_in,
                              void* d_out, int out_size) {
    const float* x       = (const float*)d_in[0];
    const float* qn_w    = (const float*)d_in[1];
    const float* qn_b    = (const float*)d_in[2];
    const float* kvn_w   = (const float*)d_in[3];
    const float* kvn_b   = (const float*)d_in[4];
    const float* q_prime = (const float*)d_in[5];
    const float* k_prime = (const float*)d_in[6];
    const float* v_prime = (const float*)d_in[7];
    const float* qW      = (const float*)d_in[8];
    const float* qb      = (const float*)d_in[9];
    const float* v1W     = (const float*)d_in[10];
    const float* v1b     = (const float*)d_in[11];
    const float* v2W     = (const float*)d_in[12];
    const float* v2b     = (const float*)d_in[13];
    float* out = (float*)d_out;

    cudaFuncSetAttribute(gemm_mma<0>, cudaFuncAttributeMaxDynamicSharedMemorySize, SMEM_BYTES);
    cudaFuncSetAttribute(gemm_mma<1>, cudaFuncAttributeMaxDynamicSharedMemorySize, SMEM_BYTES);
    cudaFuncSetAttribute(gemm_mma<2>, cudaFuncAttributeMaxDynamicSharedMemorySize, SMEM_BYTES);

    cvt_qw_kernel<<<4096, 256>>>(qW);
    gate_kernel<<<128, 256>>>(v_prime, v1W, v1b, v2W, v2b);
    ln_kernel<<<ROWS, 256>>>(x, qn_w, qn_b, kvn_w, kvn_b, k_prime);

    // qr = (xqn @ qW^T + qb) * sigmoid(q') / 32
    gemm_mma<0><<<dim3(H / BN, ROWS / BM, 1), 256, SMEM_BYTES>>>(qb, q_prime, nullptr);
    // E = exp(qr @ kr^T) + tile partial sums
    gemm_mma<1><<<dim3(SEQ / BN, SEQ / BM, BATCH), 256, SMEM_BYTES>>>(nullptr, nullptr, nullptr);
    // Zinv[b] = 1 / sum(E_b)
    zreduce_kernel<<<BATCH, 256>>>();
    // out = (E @ vr) * Zinv + xqn (f16 residual)
    gemm_mma<2><<<dim3(H / BN, SEQ / BM, BATCH), 256, SMEM_BYTES>>>(nullptr, nullptr, out);
}